// round 15
// baseline (speedup 1.0000x reference)
#include <cuda_runtime.h>
#include <cuda_fp16.h>
#include <stdint.h>

#define NH 16
#define Dh 64
#define Lq 1024
#define Bq 4
#define Eq 1024
#define BH 64

// ---- scratch (device globals) ----
__device__ __half g_query_h[4096*1024];      // query rounded fp16 (L*B, E)
__device__ __half g_win_h[3*1024*1024];      // W_in rounded
__device__ __half g_wout_h[1024*1024];       // W_out rounded
__device__ __half g_er_h[1024*64];           // relpos rounded
__device__ __half g_qh[BH*Lq*Dh];            // q rounded, scaled L2E/8 (BH,L,D)
__device__ __half g_kh[BH*Lq*Dh];            // k rounded (BH,L,D)
__device__ __half g_vh[BH*Lq*Dh];            // v rounded TRANSPOSED (BH,D,L)
__device__ __half g_qe_h[(size_t)BH*Lq*Lq];  // QE fp16, layout [l][c] (band only)
__device__ __half g_ctx_h[Lq*Bq*Eq];         // ctx rounded fp16 (L,B,E)

#define SWZ128(x) ((x) ^ (((x) >> 3) & 0x70))
#define SWZ256(x) ((x) ^ (((x) >> 4) & 0x70))

__device__ __forceinline__ void ldsm4(uint32_t (&r)[4], uint32_t addr) {
    asm volatile("ldmatrix.sync.aligned.m8n8.x4.shared.b16 {%0,%1,%2,%3}, [%4];"
                 : "=r"(r[0]), "=r"(r[1]), "=r"(r[2]), "=r"(r[3]) : "r"(addr));
}
__device__ __forceinline__ void mma_f16(float (&d)[4], const uint32_t (&a)[4],
                                        uint32_t b0, uint32_t b1) {
    asm volatile("mma.sync.aligned.m16n8k16.row.col.f32.f16.f16.f32 "
                 "{%0,%1,%2,%3}, {%4,%5,%6,%7}, {%8,%9}, {%0,%1,%2,%3};"
                 : "+f"(d[0]), "+f"(d[1]), "+f"(d[2]), "+f"(d[3])
                 : "r"(a[0]), "r"(a[1]), "r"(a[2]), "r"(a[3]), "r"(b0), "r"(b1));
}
__device__ __forceinline__ void cp16(uint32_t smem, const void* g) {
    asm volatile("cp.async.cg.shared.global [%0], [%1], 16;"
                 :: "r"(smem), "l"(g) : "memory");
}
#define CP_COMMIT() asm volatile("cp.async.commit_group;" ::: "memory")
#define CP_WAIT(N)  asm volatile("cp.async.wait_group %0;" :: "n"(N) : "memory")

__device__ __forceinline__ uint32_t packh(float a, float b) {
    __half2 t = __floats2half2_rn(a, b);
    return *(uint32_t*)&t;
}

// ---------------------------------------------------------------------------
// Prep kernel: fp32 -> fp16 round
// ---------------------------------------------------------------------------
__global__ __launch_bounds__(256) void k_round(const float* __restrict__ in,
                                               __half* __restrict__ oh, int n2) {
    int i = blockIdx.x * 256 + threadIdx.x;
    if (i < n2) {
        float2 v = ((const float2*)in)[i];
        ((__half2*)oh)[i] = __floats2half2_rn(v.x, v.y);
    }
}

// ---------------------------------------------------------------------------
// GEMM: C(128 x 128) = A(128 x K) * B(128 x K)^T, fp16 x1 operands.
// K-step 64 (stage 32KB: A 16KB + B 16KB), 3-stage cp.async pipeline.
// 256 thr, warp grid 2x4, warp tile 64x32. K % 64 == 0.
// ---------------------------------------------------------------------------
template<class Epi>
__device__ __forceinline__ void mm_f16(const __half* __restrict__ A, int lda,
                                       const __half* __restrict__ B, int ldb,
                                       int K, Epi epi)
{
    constexpr int ASZ = 16384;         // 128 x 64 fp16
    constexpr int BSZ = 16384;
    constexpr int STG = ASZ + BSZ;     // 32KB

    extern __shared__ char dsm[];
    const uint32_t su = (uint32_t)__cvta_generic_to_shared(dsm);

    const int tid  = threadIdx.x;
    const int lane = tid & 31, w = tid >> 5;
    const int m_base = (w & 1) * 64;
    const int n_base = (w >> 1) * 32;

    float acc[4][4][4];
    #pragma unroll
    for (int i = 0; i < 4; i++)
        #pragma unroll
        for (int j = 0; j < 4; j++)
            #pragma unroll
            for (int q = 0; q < 4; q++) acc[i][j][q] = 0.f;

    const uint32_t a_row = lane & 15;
    const uint32_t a_k8  = (lane >> 4) * 8;
    const uint32_t b_row = (lane & 7) + ((lane >> 4) & 1) * 8;
    const uint32_t b_k8  = ((lane >> 3) & 1) * 8;

    auto issue = [&](int s, int kb) {
        const uint32_t base = su + s * STG;
        #pragma unroll
        for (int i = 0; i < 4; i++) {
            int id = tid + i * 256; int r = id >> 3, c = id & 7;
            uint32_t off = SWZ128((uint32_t)(r * 128 + c * 16));
            cp16(base + off,       A + (size_t)r * lda + kb + c * 8);
            cp16(base + ASZ + off, B + (size_t)r * ldb + kb + c * 8);
        }
        CP_COMMIT();
    };
    auto domma = [&](int s) {
        const uint32_t sbA = su + s * STG;
        const uint32_t sbB = sbA + ASZ;
        #pragma unroll
        for (int kc = 0; kc < 4; kc++) {
            uint32_t ah[4][4];
            #pragma unroll
            for (int mt = 0; mt < 4; mt++) {
                uint32_t off = SWZ128((uint32_t)((m_base + mt * 16 + a_row) * 128
                                                 + (kc * 16 + a_k8) * 2));
                ldsm4(ah[mt], sbA + off);
            }
            uint32_t bh[2][4];
            #pragma unroll
            for (int nb = 0; nb < 2; nb++) {
                uint32_t off = SWZ128((uint32_t)((n_base + nb * 16 + b_row) * 128
                                                 + (kc * 16 + b_k8) * 2));
                ldsm4(bh[nb], sbB + off);
            }
            #pragma unroll
            for (int mt = 0; mt < 4; mt++)
                #pragma unroll
                for (int nt = 0; nt < 4; nt++) {
                    uint32_t b0 = bh[nt >> 1][(nt & 1) * 2];
                    uint32_t b1 = bh[nt >> 1][(nt & 1) * 2 + 1];
                    mma_f16(acc[mt][nt], ah[mt], b0, b1);
                }
        }
    };

    const int nk = K >> 6;
    issue(0, 0);
    if (nk > 1) issue(1, 64);
    for (int i = 0; i < nk; i++) {
        if (i + 1 < nk) { CP_WAIT(1); } else { CP_WAIT(0); }
        __syncthreads();
        if (i + 2 < nk) issue((i + 2) % 3, (i + 2) * 64);
        domma(i % 3);
    }

    #pragma unroll
    for (int mt = 0; mt < 4; mt++)
        #pragma unroll
        for (int nt = 0; nt < 4; nt++) {
            int m = m_base + mt * 16 + (lane >> 2);
            int n = n_base + nt * 8 + (lane & 3) * 2;
            epi(m,     n, make_float2(acc[mt][nt][0], acc[mt][nt][1]));
            epi(m + 8, n, make_float2(acc[mt][nt][2], acc[mt][nt][3]));
        }
}

// ---------------------------------------------------------------------------
// Epilogues
// ---------------------------------------------------------------------------
#define QSCALE 0.18033688011112042f   // (1/8) * log2(e)

struct EpiQKV {
    int m0, n0; const float* bias;
    __device__ __forceinline__ void operator()(int mi, int ni, float2 v) const {
        int m = m0 + mi, n = n0 + ni;
        float2 bb = *(const float2*)(bias + n);
        v.x += bb.x; v.y += bb.y;
        int l = m >> 2, b = m & 3;
        int sec = n >> 10, e = n & 1023, h = e >> 6, d = e & 63;
        if (sec == 0) {
            v.x *= QSCALE; v.y *= QSCALE;
            *(__half2*)(g_qh + (((b * NH + h) * Lq + l) * Dh + d)) =
                __floats2half2_rn(v.x, v.y);
        } else if (sec == 1) {
            *(__half2*)(g_kh + (((b * NH + h) * Lq + l) * Dh + d)) =
                __floats2half2_rn(v.x, v.y);
        } else {
            size_t ix = ((size_t)(b * NH + h) * Dh + d) * Lq + l;
            g_vh[ix]      = __float2half(v.x);
            g_vh[ix + Lq] = __float2half(v.y);
        }
    }
};
struct EpiStoreH {       // coalesced fp16 tile store (layout [l][c])
    __half* C; int m0, n0;
    __device__ __forceinline__ void operator()(int mi, int ni, float2 v) const {
        *(__half2*)(C + (size_t)(m0 + mi) * Lq + (n0 + ni)) =
            __floats2half2_rn(v.x, v.y);
    }
};
struct EpiBias {
    float* C; const float* bias; int m0, n0;
    __device__ __forceinline__ void operator()(int mi, int ni, float2 v) const {
        float2 bb = *(const float2*)(bias + n0 + ni);
        v.x += bb.x; v.y += bb.y;
        *(float2*)(C + (size_t)(m0 + mi) * Eq + (n0 + ni)) = v;
    }
};

// ---------------------------------------------------------------------------
__global__ __launch_bounds__(256, 2) void k_qkv(const float* __restrict__ bias) {
    EpiQKV e{(int)blockIdx.y * 128, (int)blockIdx.x * 128, bias};
    mm_f16(g_query_h + (size_t)e.m0 * Eq, Eq,
           g_win_h + (size_t)e.n0 * Eq, Eq, Eq, e);
}

__global__ __launch_bounds__(256, 2) void k_qe() {
    if (blockIdx.x + blockIdx.y < 7) return;   // band tiles only
    int bh = blockIdx.z;
    int m0 = blockIdx.y * 128, n0 = blockIdx.x * 128;
    EpiStoreH e{g_qe_h + (size_t)bh * Lq * Lq, m0, n0};
    mm_f16(g_qh + (size_t)bh * Lq * Dh + (size_t)m0 * Dh, Dh,
           g_er_h + (size_t)n0 * Dh, Dh, Dh, e);
}

__global__ __launch_bounds__(256, 2) void k_outproj(const float* __restrict__ bias,
                                                    float* __restrict__ out) {
    int m0 = blockIdx.y * 128, n0 = blockIdx.x * 128;
    EpiBias e{out, bias, m0, n0};
    mm_f16(g_ctx_h + (size_t)m0 * Eq, Eq,
           g_wout_h + (size_t)n0 * Eq, Eq, Eq, e);
}

// ---------------------------------------------------------------------------
// Fused attention, cp.async 3-stage KV pipeline (3 x 32KB dynamic smem).
// fp16 x1 K/V. Logits in exp2 domain. srel from fp16 QE, register-prefetched.
// No max tracking. exp2/pack interleaved with PV MMAs.
// ---------------------------------------------------------------------------
__global__ __launch_bounds__(256, 1) void k_attn() {
    extern __shared__ char sm[];
    const uint32_t su = (uint32_t)__cvta_generic_to_shared(sm);
    // stage s (s = nb % 3): K = s*32768, V = +16384

    const int tid = threadIdx.x, lane = tid & 31, w = tid >> 5;
    const int m0 = blockIdx.x * 128, bh = blockIdx.y;
    const int rb = w * 16;

    const __half* __restrict__ Qg = g_qh + (size_t)bh * Lq * Dh + (size_t)m0 * Dh;

    // ---- stage Q via cp.async into stage0 K area, pull frags ----
    #pragma unroll
    for (int i = 0; i < 4; i++) {
        int id = tid + i * 256; int r = id >> 3, c = id & 7;
        cp16(su + SWZ128((uint32_t)(r * 128 + c * 16)), Qg + (size_t)r * Dh + c * 8);
    }
    CP_COMMIT(); CP_WAIT(0);
    __syncthreads();
    uint32_t qh[4][4];
    {
        uint32_t arow = rb + (lane & 15);
        uint32_t ak   = (lane >> 4) * 8;
        #pragma unroll
        for (int kc = 0; kc < 4; kc++) {
            uint32_t off = SWZ128(arow * 128 + (kc * 16 + ak) * 2);
            ldsm4(qh[kc], su + off);
        }
    }
    __syncthreads();   // Q reads done before stage0 is refilled

    auto issueKV = [&](int nb) {
        const int n0 = nb * 128, s = nb % 3;
        const uint32_t base = su + s * 32768;
        #pragma unroll
        for (int i = 0; i < 4; i++) {
            int id = tid + i * 256; int r = id >> 3, c = id & 7;
            uint32_t off = SWZ128((uint32_t)(r * 128 + c * 16));
            cp16(base + off,
                 g_kh + (size_t)bh * Lq * Dh + (size_t)(n0 + r) * Dh + c * 8);
        }
        #pragma unroll
        for (int i = 0; i < 4; i++) {
            int id = tid + i * 256; int r = id >> 4, c = id & 15;
            uint32_t off = SWZ256((uint32_t)(r * 256 + c * 16));
            cp16(base + 16384 + off,
                 g_vh + ((size_t)bh * Dh + r) * Lq + n0 + c * 8);
        }
        CP_COMMIT();
    };

    float o[8][4];
    #pragma unroll
    for (int f = 0; f < 8; f++) { o[f][0]=0.f; o[f][1]=0.f; o[f][2]=0.f; o[f][3]=0.f; }
    float sum0 = 0.f, sum1 = 0.f;

    const uint32_t brow = (lane & 7) + ((lane >> 4) & 1) * 8;
    const uint32_t bk8  = ((lane >> 3) & 1) * 8;
    const int l0 = m0 + rb + (lane >> 2), l1 = l0 + 8;

    // QE rows, pre-offset so index m gives column 1023+m-l (the skew gather)
    const __half* __restrict__ q0 = g_qe_h + ((size_t)bh * Lq + l0) * Lq + (1023 - l0);
    const __half* __restrict__ q1 = g_qe_h + ((size_t)bh * Lq + l1) * Lq + (1023 - l1);

    issueKV(0);
    issueKV(1);

    for (int nb = 0; nb < 8; nb++) {
        const int n0 = nb * 128;
        const uint32_t suK = su + (nb % 3) * 32768;
        const uint32_t suV = suK + 16384;

        if (nb < 7) { CP_WAIT(1); } else { CP_WAIT(0); }
        __syncthreads();
        if (nb + 2 < 8) issueKV(nb + 2);   // 2-deep prefetch over compute

        // srel register-prefetch (guarded loads; latency hides under S-MMA)
        float sa[16][4];
        if (n0 <= m0) {
            #pragma unroll
            for (int f = 0; f < 16; f++) {
                int m = n0 + f * 8 + (lane & 3) * 2;
                sa[f][0] = (m     <= l0) ? __half2float(q0[m])     : 0.f;
                sa[f][1] = (m + 1 <= l0) ? __half2float(q0[m + 1]) : 0.f;
                sa[f][2] = (m     <= l1) ? __half2float(q1[m])     : 0.f;
                sa[f][3] = (m + 1 <= l1) ? __half2float(q1[m + 1]) : 0.f;
            }
        } else {
            #pragma unroll
            for (int f = 0; f < 16; f++) {
                sa[f][0] = 0.f; sa[f][1] = 0.f; sa[f][2] = 0.f; sa[f][3] = 0.f;
            }
        }

        // S = Q K^T (fp16 x1) — logits in exp2 domain
        float s[16][4];
        #pragma unroll
        for (int f = 0; f < 16; f++) { s[f][0]=0.f; s[f][1]=0.f; s[f][2]=0.f; s[f][3]=0.f; }
        #pragma unroll
        for (int n16 = 0; n16 < 8; n16++) {
            #pragma unroll
            for (int kc = 0; kc < 4; kc++) {
                uint32_t off = SWZ128((n16 * 16 + brow) * 128 + (kc * 16 + bk8) * 2);
                uint32_t kh4[4];
                ldsm4(kh4, suK + off);
                mma_f16(s[2*n16],   qh[kc], kh4[0], kh4[1]);
                mma_f16(s[2*n16+1], qh[kc], kh4[2], kh4[3]);
            }
        }

        // exp2 + pack + PV, interleaved per kk (MUFU overlaps HMMA)
        #pragma unroll
        for (int kk = 0; kk < 8; kk++) {
            float e00 = exp2f(s[2*kk][0]   + sa[2*kk][0]);
            float e01 = exp2f(s[2*kk][1]   + sa[2*kk][1]);
            float e10 = exp2f(s[2*kk][2]   + sa[2*kk][2]);
            float e11 = exp2f(s[2*kk][3]   + sa[2*kk][3]);
            float e20 = exp2f(s[2*kk+1][0] + sa[2*kk+1][0]);
            float e21 = exp2f(s[2*kk+1][1] + sa[2*kk+1][1]);
            float e30 = exp2f(s[2*kk+1][2] + sa[2*kk+1][2]);
            float e31 = exp2f(s[2*kk+1][3] + sa[2*kk+1][3]);
            sum0 += e00 + e01 + e20 + e21;
            sum1 += e10 + e11 + e30 + e31;
            uint32_t ahp[4];
            ahp[0] = packh(e00, e01);
            ahp[1] = packh(e10, e11);
            ahp[2] = packh(e20, e21);
            ahp[3] = packh(e30, e31);
            #pragma unroll
            for (int n16 = 0; n16 < 4; n16++) {
                uint32_t off = SWZ256((n16 * 16 + brow) * 256 + (kk * 16 + bk8) * 2);
                uint32_t vh4[4];
                ldsm4(vh4, suV + off);
                mma_f16(o[2*n16],   ahp, vh4[0], vh4[1]);
                mma_f16(o[2*n16+1], ahp, vh4[2], vh4[3]);
            }
        }
    }

    // finalize: write ctx as rounded fp16
    sum0 += __shfl_xor_sync(0xffffffffu, sum0, 1);
    sum0 += __shfl_xor_sync(0xffffffffu, sum0, 2);
    sum1 += __shfl_xor_sync(0xffffffffu, sum1, 1);
    sum1 += __shfl_xor_sync(0xffffffffu, sum1, 2);
    const float inv0 = 1.0f / sum0, inv1 = 1.0f / sum1;
    const int b = bh >> 4, h = bh & 15;
    #pragma unroll
    for (int f = 0; f < 8; f++) {
        int d = f * 8 + (lane & 3) * 2;
        *(__half2*)(g_ctx_h + (size_t)l0 * (Bq * Eq) + b * Eq + h * Dh + d) =
            __floats2half2_rn(o[f][0] * inv0, o[f][1] * inv0);
        *(__half2*)(g_ctx_h + (size_t)l1 * (Bq * Eq) + b * Eq + h * Dh + d) =
            __floats2half2_rn(o[f][2] * inv1, o[f][3] * inv1);
    }
}

// ---------------------------------------------------------------------------
extern "C" void kernel_launch(void* const* d_in, const int* in_sizes, int n_in,
                              void* d_out, int out_size)
{
    (void)in_sizes; (void)n_in; (void)out_size;
    const float* query  = (const float*)d_in[0];
    const float* relpos = (const float*)d_in[1];
    const float* w_in   = (const float*)d_in[2];
    const float* b_in   = (const float*)d_in[3];
    const float* w_out  = (const float*)d_in[4];
    const float* b_out  = (const float*)d_in[5];
    float* out = (float*)d_out;

    const int SMG = 3 * 32768;   // 98304
    cudaFuncSetAttribute(k_qkv,     cudaFuncAttributeMaxDynamicSharedMemorySize, SMG);
    cudaFuncSetAttribute(k_qe,      cudaFuncAttributeMaxDynamicSharedMemorySize, SMG);
    cudaFuncSetAttribute(k_outproj, cudaFuncAttributeMaxDynamicSharedMemorySize, SMG);
    cudaFuncSetAttribute(k_attn,    cudaFuncAttributeMaxDynamicSharedMemorySize, 98304);

    __half *p_query, *p_win, *p_wout, *p_er;
    cudaGetSymbolAddress((void**)&p_query, g_query_h);
    cudaGetSymbolAddress((void**)&p_win,   g_win_h);
    cudaGetSymbolAddress((void**)&p_wout,  g_wout_h);
    cudaGetSymbolAddress((void**)&p_er,    g_er_h);

    k_round<<<(4096*1024/2 + 255)/256, 256>>>(query, p_query, 4096*1024/2);
    k_round<<<(3*1024*1024/2 + 255)/256, 256>>>(w_in, p_win, 3*1024*1024/2);
    k_round<<<(1024*1024/2 + 255)/256, 256>>>(w_out, p_wout, 1024*1024/2);
    k_round<<<(1024*64/2 + 255)/256, 256>>>(relpos, p_er, 1024*64/2);

    k_qkv    <<<dim3(24, 32),   256, SMG>>>(b_in);
    k_qe     <<<dim3(8, 8, 64), 256, SMG>>>();
    k_attn   <<<dim3(8, 64),    256, 98304>>>();
    k_outproj<<<dim3(8, 32),    256, SMG>>>(b_out, out);
}

// round 16
// speedup vs baseline: 1.6050x; 1.6050x over previous
#include <cuda_runtime.h>
#include <cuda_fp16.h>
#include <stdint.h>

#define NH 16
#define Dh 64
#define Lq 1024
#define Bq 4
#define Eq 1024
#define BH 64

// ---- scratch (device globals) ----
__device__ __half g_query_h[4096*1024];      // query rounded fp16 (L*B, E)
__device__ __half g_win_h[3*1024*1024];      // W_in rounded
__device__ __half g_wout_h[1024*1024];       // W_out rounded
__device__ __half g_er_h[1024*64];           // relpos rounded
__device__ __half g_qh[BH*Lq*Dh];            // q rounded, scaled L2E/8 (BH,L,D)
__device__ __half g_kh[BH*Lq*Dh];            // k rounded (BH,L,D)
__device__ __half g_vh[BH*Lq*Dh];            // v rounded TRANSPOSED (BH,D,L)
__device__ __half g_qe_h[(size_t)BH*Lq*Lq + 256]; // QE fp16 [l][c] (+pad for aligned over-read)
__device__ __half g_ctx_h[Lq*Bq*Eq];         // ctx rounded fp16 (L,B,E)

#define SWZ64(x)  ((x) ^ (((x) >> 3) & 0x30))
#define SWZ128(x) ((x) ^ (((x) >> 3) & 0x70))
#define SWZ256(x) ((x) ^ (((x) >> 4) & 0x70))

__device__ __forceinline__ void ldsm4(uint32_t (&r)[4], uint32_t addr) {
    asm volatile("ldmatrix.sync.aligned.m8n8.x4.shared.b16 {%0,%1,%2,%3}, [%4];"
                 : "=r"(r[0]), "=r"(r[1]), "=r"(r[2]), "=r"(r[3]) : "r"(addr));
}
__device__ __forceinline__ void mma_f16(float (&d)[4], const uint32_t (&a)[4],
                                        uint32_t b0, uint32_t b1) {
    asm volatile("mma.sync.aligned.m16n8k16.row.col.f32.f16.f16.f32 "
                 "{%0,%1,%2,%3}, {%4,%5,%6,%7}, {%8,%9}, {%0,%1,%2,%3};"
                 : "+f"(d[0]), "+f"(d[1]), "+f"(d[2]), "+f"(d[3])
                 : "r"(a[0]), "r"(a[1]), "r"(a[2]), "r"(a[3]), "r"(b0), "r"(b1));
}
__device__ __forceinline__ void cp16(uint32_t smem, const void* g) {
    asm volatile("cp.async.cg.shared.global [%0], [%1], 16;"
                 :: "r"(smem), "l"(g) : "memory");
}
#define CP_COMMIT() asm volatile("cp.async.commit_group;" ::: "memory")
#define CP_WAIT(N)  asm volatile("cp.async.wait_group %0;" :: "n"(N) : "memory")

__device__ __forceinline__ uint32_t packh(float a, float b) {
    __half2 t = __floats2half2_rn(a, b);
    return *(uint32_t*)&t;
}

// ---------------------------------------------------------------------------
// Prep kernel: fp32 -> fp16 round
// ---------------------------------------------------------------------------
__global__ __launch_bounds__(256) void k_round(const float* __restrict__ in,
                                               __half* __restrict__ oh, int n2) {
    int i = blockIdx.x * 256 + threadIdx.x;
    if (i < n2) {
        float2 v = ((const float2*)in)[i];
        ((__half2*)oh)[i] = __floats2half2_rn(v.x, v.y);
    }
}

// ---------------------------------------------------------------------------
// GEMM: C(128 x 128) = A(128 x K) * B(128 x K)^T, fp16 x1 operands.
// cp.async 3-stage pipeline, stage = 16KB (K-step 32). 256 thr, warps 2x4.
// (R14-proven configuration)
// ---------------------------------------------------------------------------
template<class Epi>
__device__ __forceinline__ void mm_f16(const __half* __restrict__ A, int lda,
                                       const __half* __restrict__ B, int ldb,
                                       int K, Epi epi)
{
    constexpr int ASZ = 8192;
    constexpr int BSZ = 8192;
    constexpr int STG = ASZ + BSZ;   // 16KB

    extern __shared__ char dsm[];
    const uint32_t su = (uint32_t)__cvta_generic_to_shared(dsm);

    const int tid  = threadIdx.x;
    const int lane = tid & 31, w = tid >> 5;
    const int m_base = (w & 1) * 64;
    const int n_base = (w >> 1) * 32;

    float acc[4][4][4];
    #pragma unroll
    for (int i = 0; i < 4; i++)
        #pragma unroll
        for (int j = 0; j < 4; j++)
            #pragma unroll
            for (int q = 0; q < 4; q++) acc[i][j][q] = 0.f;

    const uint32_t a_row = lane & 15;
    const uint32_t a_k8  = (lane >> 4) * 8;
    const uint32_t b_row = (lane & 7) + ((lane >> 4) & 1) * 8;
    const uint32_t b_k8  = ((lane >> 3) & 1) * 8;

    auto issue = [&](int s, int kb) {
        const uint32_t base = su + s * STG;
        #pragma unroll
        for (int i = 0; i < 2; i++) {
            int id = tid + i * 256; int r = id >> 2, c = id & 3;
            uint32_t off = SWZ64((uint32_t)(r * 64 + c * 16));
            cp16(base + off,       A + (size_t)r * lda + kb + c * 8);
            cp16(base + ASZ + off, B + (size_t)r * ldb + kb + c * 8);
        }
        CP_COMMIT();
    };
    auto domma = [&](int s) {
        const uint32_t sbA = su + s * STG;
        const uint32_t sbB = sbA + ASZ;
        #pragma unroll
        for (int kc = 0; kc < 2; kc++) {
            uint32_t ah[4][4];
            #pragma unroll
            for (int mt = 0; mt < 4; mt++) {
                uint32_t off = SWZ64((uint32_t)((m_base + mt * 16 + a_row) * 64
                                                + (kc * 16 + a_k8) * 2));
                ldsm4(ah[mt], sbA + off);
            }
            uint32_t bh[2][4];
            #pragma unroll
            for (int nb = 0; nb < 2; nb++) {
                uint32_t off = SWZ64((uint32_t)((n_base + nb * 16 + b_row) * 64
                                                + (kc * 16 + b_k8) * 2));
                ldsm4(bh[nb], sbB + off);
            }
            #pragma unroll
            for (int mt = 0; mt < 4; mt++)
                #pragma unroll
                for (int nt = 0; nt < 4; nt++) {
                    uint32_t b0 = bh[nt >> 1][(nt & 1) * 2];
                    uint32_t b1 = bh[nt >> 1][(nt & 1) * 2 + 1];
                    mma_f16(acc[mt][nt], ah[mt], b0, b1);
                }
        }
    };

    const int nk = K >> 5;
    issue(0, 0);
    issue(1, 32);
    for (int i = 0; i < nk; i++) {
        if (i + 1 < nk) { CP_WAIT(1); } else { CP_WAIT(0); }
        __syncthreads();
        if (i + 2 < nk) issue((i + 2) % 3, (i + 2) * 32);
        domma(i % 3);
    }

    #pragma unroll
    for (int mt = 0; mt < 4; mt++)
        #pragma unroll
        for (int nt = 0; nt < 4; nt++) {
            int m = m_base + mt * 16 + (lane >> 2);
            int n = n_base + nt * 8 + (lane & 3) * 2;
            epi(m,     n, make_float2(acc[mt][nt][0], acc[mt][nt][1]));
            epi(m + 8, n, make_float2(acc[mt][nt][2], acc[mt][nt][3]));
        }
}

// ---------------------------------------------------------------------------
// Epilogues
// ---------------------------------------------------------------------------
#define QSCALE 0.18033688011112042f   // (1/8) * log2(e)

struct EpiQKV {
    int m0, n0; const float* bias;
    __device__ __forceinline__ void operator()(int mi, int ni, float2 v) const {
        int m = m0 + mi, n = n0 + ni;
        float2 bb = *(const float2*)(bias + n);
        v.x += bb.x; v.y += bb.y;
        int l = m >> 2, b = m & 3;
        int sec = n >> 10, e = n & 1023, h = e >> 6, d = e & 63;
        if (sec == 0) {
            v.x *= QSCALE; v.y *= QSCALE;
            *(__half2*)(g_qh + (((b * NH + h) * Lq + l) * Dh + d)) =
                __floats2half2_rn(v.x, v.y);
        } else if (sec == 1) {
            *(__half2*)(g_kh + (((b * NH + h) * Lq + l) * Dh + d)) =
                __floats2half2_rn(v.x, v.y);
        } else {
            size_t ix = ((size_t)(b * NH + h) * Dh + d) * Lq + l;
            g_vh[ix]      = __float2half(v.x);
            g_vh[ix + Lq] = __float2half(v.y);
        }
    }
};
struct EpiStoreH {       // coalesced fp16 tile store (layout [l][c])
    __half* C; int m0, n0;
    __device__ __forceinline__ void operator()(int mi, int ni, float2 v) const {
        *(__half2*)(C + (size_t)(m0 + mi) * Lq + (n0 + ni)) =
            __floats2half2_rn(v.x, v.y);
    }
};
struct EpiBias {
    float* C; const float* bias; int m0, n0;
    __device__ __forceinline__ void operator()(int mi, int ni, float2 v) const {
        float2 bb = *(const float2*)(bias + n0 + ni);
        v.x += bb.x; v.y += bb.y;
        *(float2*)(C + (size_t)(m0 + mi) * Eq + (n0 + ni)) = v;
    }
};

// ---------------------------------------------------------------------------
__global__ __launch_bounds__(256, 2) void k_qkv(const float* __restrict__ bias) {
    EpiQKV e{(int)blockIdx.y * 128, (int)blockIdx.x * 128, bias};
    mm_f16(g_query_h + (size_t)e.m0 * Eq, Eq,
           g_win_h + (size_t)e.n0 * Eq, Eq, Eq, e);
}

__global__ __launch_bounds__(256, 2) void k_qe() {
    if (blockIdx.x + blockIdx.y < 7) return;   // band tiles only
    int bh = blockIdx.z;
    int m0 = blockIdx.y * 128, n0 = blockIdx.x * 128;
    EpiStoreH e{g_qe_h + (size_t)bh * Lq * Lq, m0, n0};
    mm_f16(g_qh + (size_t)bh * Lq * Dh + (size_t)m0 * Dh, Dh,
           g_er_h + (size_t)n0 * Dh, Dh, Dh, e);
}

__global__ __launch_bounds__(256, 2) void k_outproj(const float* __restrict__ bias,
                                                    float* __restrict__ out) {
    int m0 = blockIdx.y * 128, n0 = blockIdx.x * 128;
    EpiBias e{out, bias, m0, n0};
    mm_f16(g_ctx_h + (size_t)m0 * Eq, Eq,
           g_wout_h + (size_t)n0 * Eq, Eq, Eq, e);
}

// ---------------------------------------------------------------------------
// Fused attention (R14 base), cp.async double-buffered K/V (2 x 32KB) +
// NEW: srel staged through smem with wide aligned loads (94% sector eff).
// smem: [0,65536) KV stages; [65536, 65536+36864) srel rows (288B/row).
// ---------------------------------------------------------------------------
#define SREL_ROWB 288                 // 144 halves per staged row
#define SREL_BASE 65536
#define SREL_WARP (16 * SREL_ROWB)    // 4608 B per warp

__global__ __launch_bounds__(256, 1) void k_attn() {
    extern __shared__ char sm[];
    const uint32_t su = (uint32_t)__cvta_generic_to_shared(sm);
    // KV stage s: K = s*32768, V = +16384

    const int tid = threadIdx.x, lane = tid & 31, w = tid >> 5;
    const int m0 = blockIdx.x * 128, bh = blockIdx.y;
    const int rb = w * 16;

    const __half* __restrict__ Qg = g_qh + (size_t)bh * Lq * Dh + (size_t)m0 * Dh;

    // ---- stage Q via cp.async into stage0 K area, pull frags ----
    #pragma unroll
    for (int i = 0; i < 4; i++) {
        int id = tid + i * 256; int r = id >> 3, c = id & 7;
        cp16(su + SWZ128((uint32_t)(r * 128 + c * 16)), Qg + (size_t)r * Dh + c * 8);
    }
    CP_COMMIT(); CP_WAIT(0);
    __syncthreads();
    uint32_t qh[4][4];
    {
        uint32_t arow = rb + (lane & 15);
        uint32_t ak   = (lane >> 4) * 8;
        #pragma unroll
        for (int kc = 0; kc < 4; kc++) {
            uint32_t off = SWZ128(arow * 128 + (kc * 16 + ak) * 2);
            ldsm4(qh[kc], su + off);
        }
    }
    __syncthreads();   // Q reads done before stage0 is refilled

    auto issueKV = [&](int nb) {
        const int n0 = nb * 128, s = nb & 1;
        const uint32_t base = su + s * 32768;
        #pragma unroll
        for (int i = 0; i < 4; i++) {
            int id = tid + i * 256; int r = id >> 3, c = id & 7;
            uint32_t off = SWZ128((uint32_t)(r * 128 + c * 16));
            cp16(base + off,
                 g_kh + (size_t)bh * Lq * Dh + (size_t)(n0 + r) * Dh + c * 8);
        }
        #pragma unroll
        for (int i = 0; i < 4; i++) {
            int id = tid + i * 256; int r = id >> 4, c = id & 15;
            uint32_t off = SWZ256((uint32_t)(r * 256 + c * 16));
            cp16(base + 16384 + off,
                 g_vh + ((size_t)bh * Dh + r) * Lq + n0 + c * 8);
        }
        CP_COMMIT();
    };

    float o[8][4];
    #pragma unroll
    for (int f = 0; f < 8; f++) { o[f][0]=0.f; o[f][1]=0.f; o[f][2]=0.f; o[f][3]=0.f; }
    float sum0 = 0.f, sum1 = 0.f;

    const uint32_t brow = (lane & 7) + ((lane >> 4) & 1) * 8;
    const uint32_t bk8  = ((lane >> 3) & 1) * 8;
    const int l0 = m0 + rb + (lane >> 2), l1 = l0 + 8;

    // --- srel staging constants ---
    // loader: each lane pair handles row j = lane>>1 (l = m0+rb+j)
    const int lj  = m0 + rb + (lane >> 1);
    const int dj  = (1023 - lj) & 7;                       // align-down amount (halves)
    const size_t row_al0 = ((size_t)bh * Lq + lj) * Lq + (1023 - lj) - dj; // + n0 later
    char* srl_wbase = sm + SREL_BASE + w * SREL_WARP;
    // consumer: row j0 = lane>>2 (l0), j0+8 (l1); in-row offset d0 (same for both)
    const int d0 = (1023 - l0) & 7;
    const __half* cr0 = (const __half*)(srl_wbase + (lane >> 2) * SREL_ROWB)
                        + d0 + (lane & 3) * 2;
    const __half* cr1 = (const __half*)((const char*)cr0 + 8 * SREL_ROWB);

    issueKV(0);

    for (int nb = 0; nb < 8; nb++) {
        const int n0 = nb * 128;
        const uint32_t suK = su + (nb & 1) * 32768;
        const uint32_t suV = suK + 16384;
        const bool band = (n0 <= m0);

        // srel wide loads: 9 x uint4 per lane (2 lanes per row, 288B/row)
        uint4 srl[9];
        if (band) {
            const uint4* gp = (const uint4*)(g_qe_h + row_al0 + n0);
            #pragma unroll
            for (int k = 0; k < 9; k++) srl[k] = gp[(lane & 1) + k * 2];
        }

        CP_WAIT(0);
        __syncthreads();
        if (nb < 7) issueKV(nb + 1);   // KV copies overlap this block's compute

        if (band) {
            uint4* sp = (uint4*)(srl_wbase + (lane >> 1) * SREL_ROWB);
            #pragma unroll
            for (int k = 0; k < 9; k++) sp[(lane & 1) + k * 2] = srl[k];
        }

        // S = Q K^T (fp16 x1) — logits in exp2 domain
        float s[16][4];
        #pragma unroll
        for (int f = 0; f < 16; f++) { s[f][0]=0.f; s[f][1]=0.f; s[f][2]=0.f; s[f][3]=0.f; }
        #pragma unroll
        for (int n16 = 0; n16 < 8; n16++) {
            #pragma unroll
            for (int kc = 0; kc < 4; kc++) {
                uint32_t off = SWZ128((n16 * 16 + brow) * 128 + (kc * 16 + bk8) * 2);
                uint32_t kh4[4];
                ldsm4(kh4, suK + off);
                mma_f16(s[2*n16],   qh[kc], kh4[0], kh4[1]);
                mma_f16(s[2*n16+1], qh[kc], kh4[2], kh4[3]);
            }
        }

        if (band) {
            __syncwarp();   // srel STS (same warp) visible to LDS below
            #pragma unroll
            for (int kk = 0; kk < 8; kk++) {
                const int f0 = 2 * kk, f1 = 2 * kk + 1;
                const int ma = n0 + f0 * 8 + (lane & 3) * 2;
                const int mb = n0 + f1 * 8 + (lane & 3) * 2;
                float a00 = (ma     <= l0) ? __half2float(cr0[f0*8])     : 0.f;
                float a01 = (ma + 1 <= l0) ? __half2float(cr0[f0*8 + 1]) : 0.f;
                float a10 = (ma     <= l1) ? __half2float(cr1[f0*8])     : 0.f;
                float a11 = (ma + 1 <= l1) ? __half2float(cr1[f0*8 + 1]) : 0.f;
                float a20 = (mb     <= l0) ? __half2float(cr0[f1*8])     : 0.f;
                float a21 = (mb + 1 <= l0) ? __half2float(cr0[f1*8 + 1]) : 0.f;
                float a30 = (mb     <= l1) ? __half2float(cr1[f1*8])     : 0.f;
                float a31 = (mb + 1 <= l1) ? __half2float(cr1[f1*8 + 1]) : 0.f;
                float e00 = exp2f(s[f0][0] + a00);
                float e01 = exp2f(s[f0][1] + a01);
                float e10 = exp2f(s[f0][2] + a10);
                float e11 = exp2f(s[f0][3] + a11);
                float e20 = exp2f(s[f1][0] + a20);
                float e21 = exp2f(s[f1][1] + a21);
                float e30 = exp2f(s[f1][2] + a30);
                float e31 = exp2f(s[f1][3] + a31);
                sum0 += e00 + e01 + e20 + e21;
                sum1 += e10 + e11 + e30 + e31;
                uint32_t ahp[4];
                ahp[0] = packh(e00, e01);
                ahp[1] = packh(e10, e11);
                ahp[2] = packh(e20, e21);
                ahp[3] = packh(e30, e31);
                #pragma unroll
                for (int n16 = 0; n16 < 4; n16++) {
                    uint32_t off = SWZ256((n16 * 16 + brow) * 256 + (kk * 16 + bk8) * 2);
                    uint32_t vh4[4];
                    ldsm4(vh4, suV + off);
                    mma_f16(o[2*n16],   ahp, vh4[0], vh4[1]);
                    mma_f16(o[2*n16+1], ahp, vh4[2], vh4[3]);
                }
            }
        } else {
            #pragma unroll
            for (int kk = 0; kk < 8; kk++) {
                float e00 = exp2f(s[2*kk][0]);
                float e01 = exp2f(s[2*kk][1]);
                float e10 = exp2f(s[2*kk][2]);
                float e11 = exp2f(s[2*kk][3]);
                float e20 = exp2f(s[2*kk+1][0]);
                float e21 = exp2f(s[2*kk+1][1]);
                float e30 = exp2f(s[2*kk+1][2]);
                float e31 = exp2f(s[2*kk+1][3]);
                sum0 += e00 + e01 + e20 + e21;
                sum1 += e10 + e11 + e30 + e31;
                uint32_t ahp[4];
                ahp[0] = packh(e00, e01);
                ahp[1] = packh(e10, e11);
                ahp[2] = packh(e20, e21);
                ahp[3] = packh(e30, e31);
                #pragma unroll
                for (int n16 = 0; n16 < 4; n16++) {
                    uint32_t off = SWZ256((n16 * 16 + brow) * 256 + (kk * 16 + bk8) * 2);
                    uint32_t vh4[4];
                    ldsm4(vh4, suV + off);
                    mma_f16(o[2*n16],   ahp, vh4[0], vh4[1]);
                    mma_f16(o[2*n16+1], ahp, vh4[2], vh4[3]);
                }
            }
        }
    }

    // finalize: write ctx as rounded fp16
    sum0 += __shfl_xor_sync(0xffffffffu, sum0, 1);
    sum0 += __shfl_xor_sync(0xffffffffu, sum0, 2);
    sum1 += __shfl_xor_sync(0xffffffffu, sum1, 1);
    sum1 += __shfl_xor_sync(0xffffffffu, sum1, 2);
    const float inv0 = 1.0f / sum0, inv1 = 1.0f / sum1;
    const int b = bh >> 4, h = bh & 15;
    #pragma unroll
    for (int f = 0; f < 8; f++) {
        int d = f * 8 + (lane & 3) * 2;
        *(__half2*)(g_ctx_h + (size_t)l0 * (Bq * Eq) + b * Eq + h * Dh + d) =
            __floats2half2_rn(o[f][0] * inv0, o[f][1] * inv0);
        *(__half2*)(g_ctx_h + (size_t)l1 * (Bq * Eq) + b * Eq + h * Dh + d) =
            __floats2half2_rn(o[f][2] * inv1, o[f][3] * inv1);
    }
}

// ---------------------------------------------------------------------------
extern "C" void kernel_launch(void* const* d_in, const int* in_sizes, int n_in,
                              void* d_out, int out_size)
{
    (void)in_sizes; (void)n_in; (void)out_size;
    const float* query  = (const float*)d_in[0];
    const float* relpos = (const float*)d_in[1];
    const float* w_in   = (const float*)d_in[2];
    const float* b_in   = (const float*)d_in[3];
    const float* w_out  = (const float*)d_in[4];
    const float* b_out  = (const float*)d_in[5];
    float* out = (float*)d_out;

    const int SMG = 3 * (8192 + 8192);          // 49152
    const int SMA = 65536 + 8 * 16 * 288;       // 102400
    cudaFuncSetAttribute(k_qkv,     cudaFuncAttributeMaxDynamicSharedMemorySize, SMG);
    cudaFuncSetAttribute(k_qe,      cudaFuncAttributeMaxDynamicSharedMemorySize, SMG);
    cudaFuncSetAttribute(k_outproj, cudaFuncAttributeMaxDynamicSharedMemorySize, SMG);
    cudaFuncSetAttribute(k_attn,    cudaFuncAttributeMaxDynamicSharedMemorySize, SMA);

    __half *p_query, *p_win, *p_wout, *p_er;
    cudaGetSymbolAddress((void**)&p_query, g_query_h);
    cudaGetSymbolAddress((void**)&p_win,   g_win_h);
    cudaGetSymbolAddress((void**)&p_wout,  g_wout_h);
    cudaGetSymbolAddress((void**)&p_er,    g_er_h);

    k_round<<<(4096*1024/2 + 255)/256, 256>>>(query, p_query, 4096*1024/2);
    k_round<<<(3*1024*1024/2 + 255)/256, 256>>>(w_in, p_win, 3*1024*1024/2);
    k_round<<<(1024*1024/2 + 255)/256, 256>>>(w_out, p_wout, 1024*1024/2);
    k_round<<<(1024*64/2 + 255)/256, 256>>>(relpos, p_er, 1024*64/2);

    k_qkv    <<<dim3(24, 32),   256, SMG>>>(b_in);
    k_qe     <<<dim3(8, 8, 64), 256, SMG>>>();
    k_attn   <<<dim3(8, 64),    256, SMA>>>();
    k_outproj<<<dim3(8, 32),    256, SMG>>>(b_out, out);
}

// round 17
// speedup vs baseline: 1.6859x; 1.0504x over previous
#include <cuda_runtime.h>
#include <cuda_fp16.h>
#include <stdint.h>

#define NH 16
#define Dh 64
#define Lq 1024
#define Bq 4
#define Eq 1024
#define BH 64

// ---- scratch (device globals) ----
__device__ __half g_query_h[4096*1024];      // query rounded fp16 (L*B, E)
__device__ __half g_win_h[3*1024*1024];      // W_in rounded
__device__ __half g_wout_h[1024*1024];       // W_out rounded
__device__ __half g_er_h[1024*64];           // relpos rounded
__device__ __half g_qh[BH*Lq*Dh];            // q rounded, scaled L2E/8 (BH,L,D)
__device__ __half g_kh[BH*Lq*Dh];            // k rounded (BH,L,D)
__device__ __half g_vh[BH*Lq*Dh];            // v rounded TRANSPOSED (BH,D,L)
__device__ __half g_qe_h[(size_t)BH*Lq*Lq + 256]; // QE fp16 [l][c] (+pad for aligned over-read)
__device__ __half g_ctx_h[Lq*Bq*Eq];         // ctx rounded fp16 (L,B,E)

#define SWZ64(x)  ((x) ^ (((x) >> 3) & 0x30))
#define SWZ128(x) ((x) ^ (((x) >> 3) & 0x70))
#define SWZ256(x) ((x) ^ (((x) >> 4) & 0x70))

__device__ __forceinline__ void ldsm4(uint32_t (&r)[4], uint32_t addr) {
    asm volatile("ldmatrix.sync.aligned.m8n8.x4.shared.b16 {%0,%1,%2,%3}, [%4];"
                 : "=r"(r[0]), "=r"(r[1]), "=r"(r[2]), "=r"(r[3]) : "r"(addr));
}
__device__ __forceinline__ void mma_f16(float (&d)[4], const uint32_t (&a)[4],
                                        uint32_t b0, uint32_t b1) {
    asm volatile("mma.sync.aligned.m16n8k16.row.col.f32.f16.f16.f32 "
                 "{%0,%1,%2,%3}, {%4,%5,%6,%7}, {%8,%9}, {%0,%1,%2,%3};"
                 : "+f"(d[0]), "+f"(d[1]), "+f"(d[2]), "+f"(d[3])
                 : "r"(a[0]), "r"(a[1]), "r"(a[2]), "r"(a[3]), "r"(b0), "r"(b1));
}
__device__ __forceinline__ void cp16(uint32_t smem, const void* g) {
    asm volatile("cp.async.cg.shared.global [%0], [%1], 16;"
                 :: "r"(smem), "l"(g) : "memory");
}
#define CP_COMMIT() asm volatile("cp.async.commit_group;" ::: "memory")
#define CP_WAIT(N)  asm volatile("cp.async.wait_group %0;" :: "n"(N) : "memory")

__device__ __forceinline__ uint32_t packh(float a, float b) {
    __half2 t = __floats2half2_rn(a, b);
    return *(uint32_t*)&t;
}

// ---------------------------------------------------------------------------
// Fused prep: round query / w_in / w_out / relpos to fp16 in ONE launch.
// Ranges in half2 units: q 2097152 | win 1572864 | wout 524288 | er 32768
// ---------------------------------------------------------------------------
#define PREP_Q  2097152
#define PREP_W  (PREP_Q + 1572864)    // 3670016
#define PREP_O  (PREP_W + 524288)     // 4194304
#define PREP_E  (PREP_O + 32768)      // 4227072

__global__ __launch_bounds__(256) void k_prep(const float* __restrict__ query,
                                              const float* __restrict__ w_in,
                                              const float* __restrict__ w_out,
                                              const float* __restrict__ er) {
    int i = blockIdx.x * 256 + threadIdx.x;
    const float* src; __half* dst; int base;
    if (i < PREP_Q)      { src = query; dst = g_query_h; base = 0; }
    else if (i < PREP_W) { src = w_in;  dst = g_win_h;   base = PREP_Q; }
    else if (i < PREP_O) { src = w_out; dst = g_wout_h;  base = PREP_W; }
    else if (i < PREP_E) { src = er;    dst = g_er_h;    base = PREP_O; }
    else return;
    int j = i - base;
    float2 v = ((const float2*)src)[j];
    ((__half2*)dst)[j] = __floats2half2_rn(v.x, v.y);
}

// ---------------------------------------------------------------------------
// GEMM: C(128 x 128) = A(128 x K) * B(128 x K)^T, fp16 x1 operands.
// cp.async 3-stage pipeline, stage = 16KB (K-step 32). 256 thr, warps 2x4.
// (R14-proven configuration)
// ---------------------------------------------------------------------------
template<class Epi>
__device__ __forceinline__ void mm_f16(const __half* __restrict__ A, int lda,
                                       const __half* __restrict__ B, int ldb,
                                       int K, Epi epi)
{
    constexpr int ASZ = 8192;
    constexpr int BSZ = 8192;
    constexpr int STG = ASZ + BSZ;   // 16KB

    extern __shared__ char dsm[];
    const uint32_t su = (uint32_t)__cvta_generic_to_shared(dsm);

    const int tid  = threadIdx.x;
    const int lane = tid & 31, w = tid >> 5;
    const int m_base = (w & 1) * 64;
    const int n_base = (w >> 1) * 32;

    float acc[4][4][4];
    #pragma unroll
    for (int i = 0; i < 4; i++)
        #pragma unroll
        for (int j = 0; j < 4; j++)
            #pragma unroll
            for (int q = 0; q < 4; q++) acc[i][j][q] = 0.f;

    const uint32_t a_row = lane & 15;
    const uint32_t a_k8  = (lane >> 4) * 8;
    const uint32_t b_row = (lane & 7) + ((lane >> 4) & 1) * 8;
    const uint32_t b_k8  = ((lane >> 3) & 1) * 8;

    auto issue = [&](int s, int kb) {
        const uint32_t base = su + s * STG;
        #pragma unroll
        for (int i = 0; i < 2; i++) {
            int id = tid + i * 256; int r = id >> 2, c = id & 3;
            uint32_t off = SWZ64((uint32_t)(r * 64 + c * 16));
            cp16(base + off,       A + (size_t)r * lda + kb + c * 8);
            cp16(base + ASZ + off, B + (size_t)r * ldb + kb + c * 8);
        }
        CP_COMMIT();
    };
    auto domma = [&](int s) {
        const uint32_t sbA = su + s * STG;
        const uint32_t sbB = sbA + ASZ;
        #pragma unroll
        for (int kc = 0; kc < 2; kc++) {
            uint32_t ah[4][4];
            #pragma unroll
            for (int mt = 0; mt < 4; mt++) {
                uint32_t off = SWZ64((uint32_t)((m_base + mt * 16 + a_row) * 64
                                                + (kc * 16 + a_k8) * 2));
                ldsm4(ah[mt], sbA + off);
            }
            uint32_t bh[2][4];
            #pragma unroll
            for (int nb = 0; nb < 2; nb++) {
                uint32_t off = SWZ64((uint32_t)((n_base + nb * 16 + b_row) * 64
                                                + (kc * 16 + b_k8) * 2));
                ldsm4(bh[nb], sbB + off);
            }
            #pragma unroll
            for (int mt = 0; mt < 4; mt++)
                #pragma unroll
                for (int nt = 0; nt < 4; nt++) {
                    uint32_t b0 = bh[nt >> 1][(nt & 1) * 2];
                    uint32_t b1 = bh[nt >> 1][(nt & 1) * 2 + 1];
                    mma_f16(acc[mt][nt], ah[mt], b0, b1);
                }
        }
    };

    const int nk = K >> 5;
    issue(0, 0);
    issue(1, 32);
    for (int i = 0; i < nk; i++) {
        if (i + 1 < nk) { CP_WAIT(1); } else { CP_WAIT(0); }
        __syncthreads();
        if (i + 2 < nk) issue((i + 2) % 3, (i + 2) * 32);
        domma(i % 3);
    }

    #pragma unroll
    for (int mt = 0; mt < 4; mt++)
        #pragma unroll
        for (int nt = 0; nt < 4; nt++) {
            int m = m_base + mt * 16 + (lane >> 2);
            int n = n_base + nt * 8 + (lane & 3) * 2;
            epi(m,     n, make_float2(acc[mt][nt][0], acc[mt][nt][1]));
            epi(m + 8, n, make_float2(acc[mt][nt][2], acc[mt][nt][3]));
        }
}

// ---------------------------------------------------------------------------
// Epilogues
// ---------------------------------------------------------------------------
#define QSCALE 0.18033688011112042f   // (1/8) * log2(e)

struct EpiQKV {
    int m0, n0; const float* bias;
    __device__ __forceinline__ void operator()(int mi, int ni, float2 v) const {
        int m = m0 + mi, n = n0 + ni;
        float2 bb = *(const float2*)(bias + n);
        v.x += bb.x; v.y += bb.y;
        int l = m >> 2, b = m & 3;
        int sec = n >> 10, e = n & 1023, h = e >> 6, d = e & 63;
        if (sec == 0) {
            v.x *= QSCALE; v.y *= QSCALE;
            *(__half2*)(g_qh + (((b * NH + h) * Lq + l) * Dh + d)) =
                __floats2half2_rn(v.x, v.y);
        } else if (sec == 1) {
            *(__half2*)(g_kh + (((b * NH + h) * Lq + l) * Dh + d)) =
                __floats2half2_rn(v.x, v.y);
        } else {
            size_t ix = ((size_t)(b * NH + h) * Dh + d) * Lq + l;
            g_vh[ix]      = __float2half(v.x);
            g_vh[ix + Lq] = __float2half(v.y);
        }
    }
};
struct EpiStoreH {       // coalesced fp16 tile store (layout [l][c])
    __half* C; int m0, n0;
    __device__ __forceinline__ void operator()(int mi, int ni, float2 v) const {
        *(__half2*)(C + (size_t)(m0 + mi) * Lq + (n0 + ni)) =
            __floats2half2_rn(v.x, v.y);
    }
};
struct EpiBias {
    float* C; const float* bias; int m0, n0;
    __device__ __forceinline__ void operator()(int mi, int ni, float2 v) const {
        float2 bb = *(const float2*)(bias + n0 + ni);
        v.x += bb.x; v.y += bb.y;
        *(float2*)(C + (size_t)(m0 + mi) * Eq + (n0 + ni)) = v;
    }
};

// ---------------------------------------------------------------------------
__global__ __launch_bounds__(256, 2) void k_qkv(const float* __restrict__ bias) {
    EpiQKV e{(int)blockIdx.y * 128, (int)blockIdx.x * 128, bias};
    mm_f16(g_query_h + (size_t)e.m0 * Eq, Eq,
           g_win_h + (size_t)e.n0 * Eq, Eq, Eq, e);
}

__global__ __launch_bounds__(256, 2) void k_qe() {
    if (blockIdx.x + blockIdx.y < 7) return;   // band tiles only
    int bh = blockIdx.z;
    int m0 = blockIdx.y * 128, n0 = blockIdx.x * 128;
    EpiStoreH e{g_qe_h + (size_t)bh * Lq * Lq, m0, n0};
    mm_f16(g_qh + (size_t)bh * Lq * Dh + (size_t)m0 * Dh, Dh,
           g_er_h + (size_t)n0 * Dh, Dh, Dh, e);
}

__global__ __launch_bounds__(256, 2) void k_outproj(const float* __restrict__ bias,
                                                    float* __restrict__ out) {
    int m0 = blockIdx.y * 128, n0 = blockIdx.x * 128;
    EpiBias e{out, bias, m0, n0};
    mm_f16(g_ctx_h + (size_t)m0 * Eq, Eq,
           g_wout_h + (size_t)n0 * Eq, Eq, Eq, e);
}

// ---------------------------------------------------------------------------
// Fused attention. KV double-buffered (2 x 32KB) via cp.async; srel now ALSO
// cp.async-DMA'd (rows 16B-aligned after align-down), double-buffered 2x36KB,
// same commit group / parity as KV. No register staging, no syncwarp.
// smem: [0,65536) KV stages; [65536, 65536+73728) srel stages.
// ---------------------------------------------------------------------------
#define SREL_ROWB 288                 // 144 halves per staged row
#define SREL_BASE 65536
#define SREL_WARP (16 * SREL_ROWB)    // 4608 B per warp
#define SREL_STG  (8 * SREL_WARP)     // 36864 B per stage

__global__ __launch_bounds__(256, 1) void k_attn() {
    extern __shared__ char sm[];
    const uint32_t su = (uint32_t)__cvta_generic_to_shared(sm);
    // KV stage s: K = s*32768, V = +16384

    const int tid = threadIdx.x, lane = tid & 31, w = tid >> 5;
    const int m0 = blockIdx.x * 128, bh = blockIdx.y;
    const int rb = w * 16;

    const __half* __restrict__ Qg = g_qh + (size_t)bh * Lq * Dh + (size_t)m0 * Dh;

    // ---- stage Q via cp.async into stage0 K area, pull frags ----
    #pragma unroll
    for (int i = 0; i < 4; i++) {
        int id = tid + i * 256; int r = id >> 3, c = id & 7;
        cp16(su + SWZ128((uint32_t)(r * 128 + c * 16)), Qg + (size_t)r * Dh + c * 8);
    }
    CP_COMMIT(); CP_WAIT(0);
    __syncthreads();
    uint32_t qh[4][4];
    {
        uint32_t arow = rb + (lane & 15);
        uint32_t ak   = (lane >> 4) * 8;
        #pragma unroll
        for (int kc = 0; kc < 4; kc++) {
            uint32_t off = SWZ128(arow * 128 + (kc * 16 + ak) * 2);
            ldsm4(qh[kc], su + off);
        }
    }
    __syncthreads();   // Q reads done before stage0 is refilled

    // --- srel addressing (rows 16B-aligned after align-down) ---
    // loader: lane pair handles row j = lane>>1 (l = m0+rb+j)
    const int lj  = m0 + rb + (lane >> 1);
    const int dj  = (1023 - lj) & 7;
    const __half* row_g0 = g_qe_h + ((size_t)bh * Lq + lj) * Lq + (1023 - lj) - dj;
    const uint32_t srl_w = su + SREL_BASE + w * SREL_WARP
                         + (lane >> 1) * SREL_ROWB + (lane & 1) * 16;
    // consumer: rows l0 = m0+rb+(lane>>2), l1 = l0+8; in-row offset d0
    const int l0 = m0 + rb + (lane >> 2), l1 = l0 + 8;
    const int d0 = (1023 - l0) & 7;

    auto issueKV = [&](int nb) {
        const int n0 = nb * 128, s = nb & 1;
        const uint32_t base = su + s * 32768;
        #pragma unroll
        for (int i = 0; i < 4; i++) {
            int id = tid + i * 256; int r = id >> 3, c = id & 7;
            uint32_t off = SWZ128((uint32_t)(r * 128 + c * 16));
            cp16(base + off,
                 g_kh + (size_t)bh * Lq * Dh + (size_t)(n0 + r) * Dh + c * 8);
        }
        #pragma unroll
        for (int i = 0; i < 4; i++) {
            int id = tid + i * 256; int r = id >> 4, c = id & 15;
            uint32_t off = SWZ256((uint32_t)(r * 256 + c * 16));
            cp16(base + 16384 + off,
                 g_vh + ((size_t)bh * Dh + r) * Lq + n0 + c * 8);
        }
        if (n0 <= m0) {   // srel DMA for this block (per-warp rows all in band range)
            const uint4* gp = (const uint4*)(row_g0 + n0) + (lane & 1);
            const uint32_t sp = srl_w + s * SREL_STG;
            #pragma unroll
            for (int k = 0; k < 9; k++)
                cp16(sp + (uint32_t)k * 32, gp + k * 2);
        }
        CP_COMMIT();
    };

    float o[8][4];
    #pragma unroll
    for (int f = 0; f < 8; f++) { o[f][0]=0.f; o[f][1]=0.f; o[f][2]=0.f; o[f][3]=0.f; }
    float sum0 = 0.f, sum1 = 0.f;

    const uint32_t brow = (lane & 7) + ((lane >> 4) & 1) * 8;
    const uint32_t bk8  = ((lane >> 3) & 1) * 8;

    issueKV(0);

    for (int nb = 0; nb < 8; nb++) {
        const int n0 = nb * 128;
        const uint32_t suK = su + (nb & 1) * 32768;
        const uint32_t suV = suK + 16384;
        const bool band = (n0 <= m0);

        CP_WAIT(0);
        __syncthreads();
        if (nb < 7) issueKV(nb + 1);   // KV+srel copies overlap this block's compute

        // S = Q K^T (fp16 x1) — logits in exp2 domain
        float s[16][4];
        #pragma unroll
        for (int f = 0; f < 16; f++) { s[f][0]=0.f; s[f][1]=0.f; s[f][2]=0.f; s[f][3]=0.f; }
        #pragma unroll
        for (int n16 = 0; n16 < 8; n16++) {
            #pragma unroll
            for (int kc = 0; kc < 4; kc++) {
                uint32_t off = SWZ128((n16 * 16 + brow) * 128 + (kc * 16 + bk8) * 2);
                uint32_t kh4[4];
                ldsm4(kh4, suK + off);
                mma_f16(s[2*n16],   qh[kc], kh4[0], kh4[1]);
                mma_f16(s[2*n16+1], qh[kc], kh4[2], kh4[3]);
            }
        }

        if (band) {
            const __half* cr0 = (const __half*)(sm + SREL_BASE + (nb & 1) * SREL_STG
                                + w * SREL_WARP + (lane >> 2) * SREL_ROWB)
                                + d0 + (lane & 3) * 2;
            const __half* cr1 = (const __half*)((const char*)cr0 + 8 * SREL_ROWB);
            #pragma unroll
            for (int kk = 0; kk < 8; kk++) {
                const int f0 = 2 * kk, f1 = 2 * kk + 1;
                const int ma = n0 + f0 * 8 + (lane & 3) * 2;
                const int mb = n0 + f1 * 8 + (lane & 3) * 2;
                float a00 = (ma     <= l0) ? __half2float(cr0[f0*8])     : 0.f;
                float a01 = (ma + 1 <= l0) ? __half2float(cr0[f0*8 + 1]) : 0.f;
                float a10 = (ma     <= l1) ? __half2float(cr1[f0*8])     : 0.f;
                float a11 = (ma + 1 <= l1) ? __half2float(cr1[f0*8 + 1]) : 0.f;
                float a20 = (mb     <= l0) ? __half2float(cr0[f1*8])     : 0.f;
                float a21 = (mb + 1 <= l0) ? __half2float(cr0[f1*8 + 1]) : 0.f;
                float a30 = (mb     <= l1) ? __half2float(cr1[f1*8])     : 0.f;
                float a31 = (mb + 1 <= l1) ? __half2float(cr1[f1*8 + 1]) : 0.f;
                float e00 = exp2f(s[f0][0] + a00);
                float e01 = exp2f(s[f0][1] + a01);
                float e10 = exp2f(s[f0][2] + a10);
                float e11 = exp2f(s[f0][3] + a11);
                float e20 = exp2f(s[f1][0] + a20);
                float e21 = exp2f(s[f1][1] + a21);
                float e30 = exp2f(s[f1][2] + a30);
                float e31 = exp2f(s[f1][3] + a31);
                sum0 += e00 + e01 + e20 + e21;
                sum1 += e10 + e11 + e30 + e31;
                uint32_t ahp[4];
                ahp[0] = packh(e00, e01);
                ahp[1] = packh(e10, e11);
                ahp[2] = packh(e20, e21);
                ahp[3] = packh(e30, e31);
                #pragma unroll
                for (int n16 = 0; n16 < 4; n16++) {
                    uint32_t off = SWZ256((n16 * 16 + brow) * 256 + (kk * 16 + bk8) * 2);
                    uint32_t vh4[4];
                    ldsm4(vh4, suV + off);
                    mma_f16(o[2*n16],   ahp, vh4[0], vh4[1]);
                    mma_f16(o[2*n16+1], ahp, vh4[2], vh4[3]);
                }
            }
        } else {
            #pragma unroll
            for (int kk = 0; kk < 8; kk++) {
                float e00 = exp2f(s[2*kk][0]);
                float e01 = exp2f(s[2*kk][1]);
                float e10 = exp2f(s[2*kk][2]);
                float e11 = exp2f(s[2*kk][3]);
                float e20 = exp2f(s[2*kk+1][0]);
                float e21 = exp2f(s[2*kk+1][1]);
                float e30 = exp2f(s[2*kk+1][2]);
                float e31 = exp2f(s[2*kk+1][3]);
                sum0 += e00 + e01 + e20 + e21;
                sum1 += e10 + e11 + e30 + e31;
                uint32_t ahp[4];
                ahp[0] = packh(e00, e01);
                ahp[1] = packh(e10, e11);
                ahp[2] = packh(e20, e21);
                ahp[3] = packh(e30, e31);
                #pragma unroll
                for (int n16 = 0; n16 < 4; n16++) {
                    uint32_t off = SWZ256((n16 * 16 + brow) * 256 + (kk * 16 + bk8) * 2);
                    uint32_t vh4[4];
                    ldsm4(vh4, suV + off);
                    mma_f16(o[2*n16],   ahp, vh4[0], vh4[1]);
                    mma_f16(o[2*n16+1], ahp, vh4[2], vh4[3]);
                }
            }
        }
    }

    // finalize: write ctx as rounded fp16
    sum0 += __shfl_xor_sync(0xffffffffu, sum0, 1);
    sum0 += __shfl_xor_sync(0xffffffffu, sum0, 2);
    sum1 += __shfl_xor_sync(0xffffffffu, sum1, 1);
    sum1 += __shfl_xor_sync(0xffffffffu, sum1, 2);
    const float inv0 = 1.0f / sum0, inv1 = 1.0f / sum1;
    const int b = bh >> 4, h = bh & 15;
    #pragma unroll
    for (int f = 0; f < 8; f++) {
        int d = f * 8 + (lane & 3) * 2;
        *(__half2*)(g_ctx_h + (size_t)l0 * (Bq * Eq) + b * Eq + h * Dh + d) =
            __floats2half2_rn(o[f][0] * inv0, o[f][1] * inv0);
        *(__half2*)(g_ctx_h + (size_t)l1 * (Bq * Eq) + b * Eq + h * Dh + d) =
            __floats2half2_rn(o[f][2] * inv1, o[f][3] * inv1);
    }
}

// ---------------------------------------------------------------------------
extern "C" void kernel_launch(void* const* d_in, const int* in_sizes, int n_in,
                              void* d_out, int out_size)
{
    (void)in_sizes; (void)n_in; (void)out_size;
    const float* query  = (const float*)d_in[0];
    const float* relpos = (const float*)d_in[1];
    const float* w_in   = (const float*)d_in[2];
    const float* b_in   = (const float*)d_in[3];
    const float* w_out  = (const float*)d_in[4];
    const float* b_out  = (const float*)d_in[5];
    float* out = (float*)d_out;

    const int SMG = 3 * (8192 + 8192);          // 49152
    const int SMA = 65536 + 2 * SREL_STG;       // 139264
    cudaFuncSetAttribute(k_qkv,     cudaFuncAttributeMaxDynamicSharedMemorySize, SMG);
    cudaFuncSetAttribute(k_qe,      cudaFuncAttributeMaxDynamicSharedMemorySize, SMG);
    cudaFuncSetAttribute(k_outproj, cudaFuncAttributeMaxDynamicSharedMemorySize, SMG);
    cudaFuncSetAttribute(k_attn,    cudaFuncAttributeMaxDynamicSharedMemorySize, SMA);

    k_prep   <<<(PREP_E + 255)/256, 256>>>(query, w_in, w_out, relpos);
    k_qkv    <<<dim3(24, 32),   256, SMG>>>(b_in);
    k_qe     <<<dim3(8, 8, 64), 256, SMG>>>();
    k_attn   <<<dim3(8, 64),    256, SMA>>>();
    k_outproj<<<dim3(8, 32),    256, SMG>>>(b_out, out);
}